// round 14
// baseline (speedup 1.0000x reference)
#include <cuda_runtime.h>
#include <cuda_fp16.h>

// Problem constants (fixed by the dataset): B=16384, F=256, T=512, D=7, C=4
#define N_FEATS     256
#define N_TREES     512
#define DEPTH       7
#define TOTAL_NODES 130048      // T * (2^(D+1) - 2)
#define N_LEAVES    131072      // T * 2^(D+1)
#define MAX_B       16384

// Level offsets: off(l) = T*(2^l - 2). Levels 1..4 occupy [0, 15360).
#define SHALLOW_NODES 15360     // 512*(2+4+8+16)
#define DEEP_NODES    114688    // 512*(32+64+128)

#define TPB             256
#define WARPS_PER_CTA   8
#define SAMPLES_PER_CTA 32
#define HALVES          2
#define TREES_PER_HALF  (N_TREES / HALVES)                 // 256
#define TREES_PER_WARP  (TREES_PER_HALF / WARPS_PER_CTA)   // 32 == warp size
#define NT              8        // ILP sweet spot (16 spills — round 11)

// Prep op-space: A = pack14 (int2 x4/op), B = u8 feats (x4/op), C = leaf (x2/op)
#define PREP_A_OPS   (SHALLOW_NODES / 4)               // 3840
#define PREP_B_OPS   (DEEP_NODES / 4)                  // 28672
#define PREP_C_OPS   (N_LEAVES / 2)                    // 65536
#define PREP_TOTAL   (PREP_A_OPS + PREP_B_OPS + PREP_C_OPS)   // 98048
// 256 blocks: >148 SMs (full coverage) AND 2 independent ops/thread (MLP 2).
#define PREP_BLOCKS  256
#define PREP_THREADS (PREP_BLOCKS * TPB)               // 65536
#define PREP_ITERS   2                                 // 131072 >= 98048

// Levels 1-4: fused (feature, f32 bias) int2 — per-tree block <= 1 line.
__device__ int2 g_packed14[SHALLOW_NODES];
// Levels 5-7: feature ids as u8 — level-7 per-tree block = 128B = ONE line.
__device__ unsigned char g_feat_u8[DEEP_NODES];
// Leaf table as half4 (8B). Value-only compression, rel_err ~2e-4.
__device__ uint2 g_leaf_h[N_LEAVES];
// Per-half partial sums.
__device__ float4 g_part[HALVES * MAX_B];

// Prep: one full wave of blocks + 2 independent ops per thread.
__global__ __launch_bounds__(TPB) void prep_kernel(
    const int*    __restrict__ nodes,
    const float*  __restrict__ biases,
    const float4* __restrict__ leaf)
{
    const int gtid = blockIdx.x * TPB + threadIdx.x;
    #pragma unroll
    for (int k = 0; k < PREP_ITERS; k++) {
        int op = gtid + k * PREP_THREADS;
        if (op < PREP_A_OPS) {
            int i = op * 4;
            int4   n = __ldg((const int4*)(nodes + i));
            float4 b = __ldg((const float4*)(biases + i));
            int4 lo = make_int4(n.x, __float_as_int(b.x), n.y, __float_as_int(b.y));
            int4 hi = make_int4(n.z, __float_as_int(b.z), n.w, __float_as_int(b.w));
            int4* dst = (int4*)(g_packed14 + i);
            dst[0] = lo; dst[1] = hi;
        } else if (op < PREP_A_OPS + PREP_B_OPS) {
            int i = (op - PREP_A_OPS) * 4;
            int4 n = __ldg((const int4*)(nodes + SHALLOW_NODES + i));
            unsigned v = (unsigned)(n.x & 255) | ((unsigned)(n.y & 255) << 8)
                       | ((unsigned)(n.z & 255) << 16) | ((unsigned)(n.w & 255) << 24);
            ((unsigned*)g_feat_u8)[i >> 2] = v;
        } else if (op < PREP_TOTAL) {
            int i = (op - PREP_A_OPS - PREP_B_OPS) * 2;
            float4 v0 = __ldg(&leaf[i]);
            float4 v1 = __ldg(&leaf[i + 1]);
            __half2 h0 = __float22half2_rn(make_float2(v0.x, v0.y));
            __half2 h1 = __float22half2_rn(make_float2(v0.z, v0.w));
            __half2 h2 = __float22half2_rn(make_float2(v1.x, v1.y));
            __half2 h3 = __float22half2_rn(make_float2(v1.z, v1.w));
            uint4 o;
            o.x = *reinterpret_cast<unsigned*>(&h0);
            o.y = *reinterpret_cast<unsigned*>(&h1);
            o.z = *reinterpret_cast<unsigned*>(&h2);
            o.w = *reinterpret_cast<unsigned*>(&h3);
            ((uint4*)g_leaf_h)[i >> 1] = o;
        }
    }
}

__global__ __launch_bounds__(TPB) void tree_kernel(
    const float*  __restrict__ x,            // (B, 256) row-major
    const int*    __restrict__ root_nodes,   // (T,)
    const float*  __restrict__ root_biases,  // (T,)
    const int*    __restrict__ tree_indices, // (T,) = 2*t
    const float*  __restrict__ biases_flat,  // (TOTAL_NODES,) original
    int B)
{
    // Feature-major x tile: xs[f*32 + local_sample]; bank = local_sample ->
    // conflict-free LDS for arbitrary feature indices. Reused for reduction.
    __shared__ float xs[N_FEATS * SAMPLES_PER_CTA];   // 32 KB
    __shared__ float tmp[SAMPLES_PER_CTA][33];        // transpose tile

    const int tid  = threadIdx.x;
    const int lane = tid & 31;
    const int w    = tid >> 5;
    const int s0   = blockIdx.x * SAMPLES_PER_CTA;
    const int half = blockIdx.y;

    // In-CTA transpose staging: row-major gmem -> feature-major smem.
    {
        const int cA = tid & 31;
        const int rA = tid >> 5;
        #pragma unroll
        for (int cf = 0; cf < N_FEATS; cf += 32) {
            #pragma unroll
            for (int k = 0; k < 4; k++) {
                int r = rA + k * 8;
                tmp[r][cA] = x[(s0 + r) * N_FEATS + cf + cA];
            }
            __syncthreads();
            #pragma unroll
            for (int k = 0; k < 4; k++) {
                int c = w + k * 8;
                xs[(cf + c) * 32 + lane] = tmp[lane][c];
            }
            __syncthreads();
        }
    }

    float a0 = 0.f, a1 = 0.f, a2 = 0.f, a3 = 0.f;
    const int tbase = half * TREES_PER_HALF + w * TREES_PER_WARP;

    // Per-warp root metadata, one tree per lane, 2 shuffles per tree.
    const int   rn_ti = __ldg(&root_nodes[tbase + lane])
                      | (__ldg(&tree_indices[tbase + lane]) << 16);
    const float rb_l  = __ldg(&root_biases[tbase + lane]);

    for (int tt = 0; tt < TREES_PER_WARP; tt += NT) {
        int idx[NT];

        #pragma unroll
        for (int j = 0; j < NT; j++) {
            int   m  = __shfl_sync(0xffffffffu, rn_ti, tt + j);
            float rb = __shfl_sync(0xffffffffu, rb_l,  tt + j);
            int   rf = m & 0xffff;
            int   ti = m >> 16;
            idx[j] = ti + (xs[rf * 32 + lane] < rb ? 1 : 0);
        }

        // Levels 1..7 (level-l block starts at T*(2^l - 2); idx is GLOBAL).
        // Branchless, independent gathers: MLP hides L1 latency.
        int off = 0;
        #pragma unroll
        for (int l = 1; l <= DEPTH; l++) {
            if (l <= 4) {
                #pragma unroll
                for (int j = 0; j < NT; j++) {
                    int2 e = __ldg(&g_packed14[off + idx[j]]);
                    float f = xs[e.x * 32 + lane];
                    idx[j] = 2 * idx[j] + (f < __int_as_float(e.y) ? 1 : 0);
                }
            } else {
                #pragma unroll
                for (int j = 0; j < NT; j++) {
                    int g = off + idx[j];
                    int fe = (int)__ldg(&g_feat_u8[g - SHALLOW_NODES]);
                    float b = __ldg(&biases_flat[g]);
                    float f = xs[fe * 32 + lane];
                    idx[j] = 2 * idx[j] + (f < b ? 1 : 0);
                }
            }
            off += N_TREES << l;
        }

        // Leaf accumulate: one LDG.64 (half4) per tree, fp32 accumulation.
        #pragma unroll
        for (int j = 0; j < NT; j++) {
            uint2 p = __ldg(&g_leaf_h[idx[j]]);
            float2 lo = __half22float2(*reinterpret_cast<__half2*>(&p.x));
            float2 hi = __half22float2(*reinterpret_cast<__half2*>(&p.y));
            a0 += lo.x; a1 += lo.y; a2 += hi.x; a3 += hi.y;
        }
    }

    // Deterministic cross-warp reduction, reusing xs as scratch.
    __syncthreads();
    float* red = xs;
    red[(w * SAMPLES_PER_CTA + lane) * 4 + 0] = a0;
    red[(w * SAMPLES_PER_CTA + lane) * 4 + 1] = a1;
    red[(w * SAMPLES_PER_CTA + lane) * 4 + 2] = a2;
    red[(w * SAMPLES_PER_CTA + lane) * 4 + 3] = a3;
    __syncthreads();

    if (w == 0) {
        float4 r = make_float4(0.f, 0.f, 0.f, 0.f);
        #pragma unroll
        for (int ww = 0; ww < WARPS_PER_CTA; ww++) {
            const float* p = red + (ww * SAMPLES_PER_CTA + lane) * 4;
            r.x += p[0]; r.y += p[1]; r.z += p[2]; r.w += p[3];
        }
        g_part[half * B + s0 + lane] = r;
    }
}

__global__ void reduce_kernel(float4* __restrict__ out, int B) {
    int i = blockIdx.x * blockDim.x + threadIdx.x;
    if (i < B) {
        float4 a = g_part[i];
        float4 b = g_part[B + i];
        out[i] = make_float4(a.x + b.x, a.y + b.y, a.z + b.z, a.w + b.w);
    }
}

extern "C" void kernel_launch(void* const* d_in, const int* in_sizes, int n_in,
                              void* d_out, int out_size) {
    const float* x            = (const float*)d_in[0];
    const int*   root_nodes   = (const int*)  d_in[1];
    const float* root_biases  = (const float*)d_in[2];
    const int*   tree_indices = (const int*)  d_in[3];
    const int*   nodes_flat   = (const int*)  d_in[4];
    const float* biases_flat  = (const float*)d_in[5];
    const float4* leaf        = (const float4*)d_in[6];
    float4* out               = (float4*)d_out;

    const int B = in_sizes[0] / N_FEATS;   // 16384

    cudaFuncSetAttribute(tree_kernel,
                         cudaFuncAttributePreferredSharedMemoryCarveout, 100);

    prep_kernel<<<PREP_BLOCKS, TPB>>>(nodes_flat, biases_flat, leaf);

    dim3 grid(B / SAMPLES_PER_CTA, HALVES);
    tree_kernel<<<grid, TPB>>>(x, root_nodes, root_biases, tree_indices,
                               biases_flat, B);

    reduce_kernel<<<(B + TPB - 1) / TPB, TPB>>>(out, B);
}

// round 15
// speedup vs baseline: 1.0442x; 1.0442x over previous
#include <cuda_runtime.h>
#include <cuda_fp16.h>

// Problem constants (fixed by the dataset): B=16384, F=256, T=512, D=7, C=4
#define N_FEATS     256
#define N_TREES     512
#define DEPTH       7
#define TOTAL_NODES 130048      // T * (2^(D+1) - 2)
#define N_LEAVES    131072      // T * 2^(D+1)
#define MAX_B       16384

// Level offsets: off(l) = T*(2^l - 2). Levels 1..4 occupy [0, 15360).
#define SHALLOW_NODES 15360     // 512*(2+4+8+16)
#define DEEP_NODES    114688    // 512*(32+64+128)

#define TPB             256
#define WARPS_PER_CTA   8
#define SAMPLES_PER_CTA 32
#define HALVES          2
#define TREES_PER_HALF  (N_TREES / HALVES)                 // 256
#define TREES_PER_WARP  (TREES_PER_HALF / WARPS_PER_CTA)   // 32 == warp size
#define NT              8        // ILP sweet spot (16 spills — round 11)

// Levels 1-4: fused (feature, f32 bias) int2 — per-tree block <= 1 line.
__device__ int2 g_packed14[SHALLOW_NODES];
// Levels 5-7: feature ids as u8 — level-7 per-tree block = 128B = ONE line.
__device__ unsigned char g_feat_u8[DEEP_NODES];
// Leaf table as half4 (8B). Value-only compression, rel_err ~2e-4.
__device__ uint2 g_leaf_h[N_LEAVES];
// Per-half partial sums.
__device__ float4 g_part[HALVES * MAX_B];

// Prep (383 blocks — empirically fastest of 96/256/383 configs):
//  blk [0,15):    pack levels 1-4, 4 entries/thread   (15*256*4  = 15360)
//  blk [15,127):  u8 features l5-7, 4 entries/thread  (112*256*4 = 114688)
//  blk [127,383): leaf fp32->fp16, 2 leaves/thread    (256*256*2 = 131072)
__global__ __launch_bounds__(TPB) void prep_kernel(
    const int*    __restrict__ nodes,
    const float*  __restrict__ biases,
    const float4* __restrict__ leaf)
{
    const int blk = blockIdx.x;
    const int tid = threadIdx.x;
    if (blk < 15) {
        int i = (blk * TPB + tid) * 4;
        int4   n = __ldg((const int4*)(nodes + i));
        float4 b = __ldg((const float4*)(biases + i));
        int4 lo = make_int4(n.x, __float_as_int(b.x), n.y, __float_as_int(b.y));
        int4 hi = make_int4(n.z, __float_as_int(b.z), n.w, __float_as_int(b.w));
        int4* dst = (int4*)(g_packed14 + i);
        dst[0] = lo; dst[1] = hi;
    } else if (blk < 127) {
        int i = ((blk - 15) * TPB + tid) * 4;
        int4 n = __ldg((const int4*)(nodes + SHALLOW_NODES + i));
        unsigned v = (unsigned)(n.x & 255) | ((unsigned)(n.y & 255) << 8)
                   | ((unsigned)(n.z & 255) << 16) | ((unsigned)(n.w & 255) << 24);
        ((unsigned*)g_feat_u8)[i >> 2] = v;
    } else {
        int i = ((blk - 127) * TPB + tid) * 2;
        float4 v0 = __ldg(&leaf[i]);
        float4 v1 = __ldg(&leaf[i + 1]);
        __half2 h0 = __float22half2_rn(make_float2(v0.x, v0.y));
        __half2 h1 = __float22half2_rn(make_float2(v0.z, v0.w));
        __half2 h2 = __float22half2_rn(make_float2(v1.x, v1.y));
        __half2 h3 = __float22half2_rn(make_float2(v1.z, v1.w));
        uint4 o;
        o.x = *reinterpret_cast<unsigned*>(&h0);
        o.y = *reinterpret_cast<unsigned*>(&h1);
        o.z = *reinterpret_cast<unsigned*>(&h2);
        o.w = *reinterpret_cast<unsigned*>(&h3);
        ((uint4*)g_leaf_h)[i >> 1] = o;
    }
}

__global__ __launch_bounds__(TPB) void tree_kernel(
    const float*  __restrict__ x,            // (B, 256) row-major
    const int*    __restrict__ root_nodes,   // (T,)
    const float*  __restrict__ root_biases,  // (T,)
    const int*    __restrict__ tree_indices, // (T,) = 2*t
    const float*  __restrict__ biases_flat,  // (TOTAL_NODES,) original
    int B)
{
    // Feature-major x tile: xs[f*32 + local_sample]; bank = local_sample ->
    // conflict-free LDS for arbitrary feature indices. Reused for reduction.
    __shared__ float xs[N_FEATS * SAMPLES_PER_CTA];   // 32 KB
    __shared__ float tmp[SAMPLES_PER_CTA][33];        // transpose tile

    const int tid  = threadIdx.x;
    const int lane = tid & 31;
    const int w    = tid >> 5;
    const int s0   = blockIdx.x * SAMPLES_PER_CTA;
    const int half = blockIdx.y;

    // In-CTA transpose staging: row-major gmem -> feature-major smem.
    {
        const int cA = tid & 31;
        const int rA = tid >> 5;
        #pragma unroll
        for (int cf = 0; cf < N_FEATS; cf += 32) {
            #pragma unroll
            for (int k = 0; k < 4; k++) {
                int r = rA + k * 8;
                tmp[r][cA] = x[(s0 + r) * N_FEATS + cf + cA];
            }
            __syncthreads();
            #pragma unroll
            for (int k = 0; k < 4; k++) {
                int c = w + k * 8;
                xs[(cf + c) * 32 + lane] = tmp[lane][c];
            }
            __syncthreads();
        }
    }

    float a0 = 0.f, a1 = 0.f, a2 = 0.f, a3 = 0.f;
    const int tbase = half * TREES_PER_HALF + w * TREES_PER_WARP;

    // Per-warp root metadata, one tree per lane, 2 shuffles per tree.
    const int   rn_ti = __ldg(&root_nodes[tbase + lane])
                      | (__ldg(&tree_indices[tbase + lane]) << 16);
    const float rb_l  = __ldg(&root_biases[tbase + lane]);

    for (int tt = 0; tt < TREES_PER_WARP; tt += NT) {
        int idx[NT];

        #pragma unroll
        for (int j = 0; j < NT; j++) {
            int   m  = __shfl_sync(0xffffffffu, rn_ti, tt + j);
            float rb = __shfl_sync(0xffffffffu, rb_l,  tt + j);
            int   rf = m & 0xffff;
            int   ti = m >> 16;
            idx[j] = ti + (xs[rf * 32 + lane] < rb ? 1 : 0);
        }

        // Levels 1..7 (level-l block starts at T*(2^l - 2); idx is GLOBAL).
        // Branchless, independent gathers: MLP hides L1 latency.
        int off = 0;
        #pragma unroll
        for (int l = 1; l <= DEPTH; l++) {
            if (l <= 4) {
                #pragma unroll
                for (int j = 0; j < NT; j++) {
                    int2 e = __ldg(&g_packed14[off + idx[j]]);
                    float f = xs[e.x * 32 + lane];
                    idx[j] = 2 * idx[j] + (f < __int_as_float(e.y) ? 1 : 0);
                }
            } else {
                #pragma unroll
                for (int j = 0; j < NT; j++) {
                    int g = off + idx[j];
                    int fe = (int)__ldg(&g_feat_u8[g - SHALLOW_NODES]);
                    float b = __ldg(&biases_flat[g]);
                    float f = xs[fe * 32 + lane];
                    idx[j] = 2 * idx[j] + (f < b ? 1 : 0);
                }
            }
            off += N_TREES << l;
        }

        // Leaf accumulate: one LDG.64 (half4) per tree, fp32 accumulation.
        #pragma unroll
        for (int j = 0; j < NT; j++) {
            uint2 p = __ldg(&g_leaf_h[idx[j]]);
            float2 lo = __half22float2(*reinterpret_cast<__half2*>(&p.x));
            float2 hi = __half22float2(*reinterpret_cast<__half2*>(&p.y));
            a0 += lo.x; a1 += lo.y; a2 += hi.x; a3 += hi.y;
        }
    }

    // Deterministic cross-warp reduction, reusing xs as scratch.
    __syncthreads();
    float* red = xs;
    red[(w * SAMPLES_PER_CTA + lane) * 4 + 0] = a0;
    red[(w * SAMPLES_PER_CTA + lane) * 4 + 1] = a1;
    red[(w * SAMPLES_PER_CTA + lane) * 4 + 2] = a2;
    red[(w * SAMPLES_PER_CTA + lane) * 4 + 3] = a3;
    __syncthreads();

    if (w == 0) {
        float4 r = make_float4(0.f, 0.f, 0.f, 0.f);
        #pragma unroll
        for (int ww = 0; ww < WARPS_PER_CTA; ww++) {
            const float* p = red + (ww * SAMPLES_PER_CTA + lane) * 4;
            r.x += p[0]; r.y += p[1]; r.z += p[2]; r.w += p[3];
        }
        g_part[half * B + s0 + lane] = r;
    }
}

__global__ void reduce_kernel(float4* __restrict__ out, int B) {
    int i = blockIdx.x * blockDim.x + threadIdx.x;
    if (i < B) {
        float4 a = g_part[i];
        float4 b = g_part[B + i];
        out[i] = make_float4(a.x + b.x, a.y + b.y, a.z + b.z, a.w + b.w);
    }
}

extern "C" void kernel_launch(void* const* d_in, const int* in_sizes, int n_in,
                              void* d_out, int out_size) {
    const float* x            = (const float*)d_in[0];
    const int*   root_nodes   = (const int*)  d_in[1];
    const float* root_biases  = (const float*)d_in[2];
    const int*   tree_indices = (const int*)  d_in[3];
    const int*   nodes_flat   = (const int*)  d_in[4];
    const float* biases_flat  = (const float*)d_in[5];
    const float4* leaf        = (const float4*)d_in[6];
    float4* out               = (float4*)d_out;

    const int B = in_sizes[0] / N_FEATS;   // 16384

    // EXPERIMENT (single variable vs round-8 best): carveout 100 -> 80.
    // 80% of 228KB = 182KB smem window -> 5 CTAs/SM (40 warps) instead of 6
    // (48), leaving ~46KB of L1D instead of ~10KB for the hot gather tables.
    cudaFuncSetAttribute(tree_kernel,
                         cudaFuncAttributePreferredSharedMemoryCarveout, 80);

    prep_kernel<<<383, TPB>>>(nodes_flat, biases_flat, leaf);

    dim3 grid(B / SAMPLES_PER_CTA, HALVES);
    tree_kernel<<<grid, TPB>>>(x, root_nodes, root_biases, tree_indices,
                               biases_flat, B);

    reduce_kernel<<<(B + TPB - 1) / TPB, TPB>>>(out, B);
}

// round 16
// speedup vs baseline: 1.1946x; 1.1440x over previous
#include <cuda_runtime.h>
#include <cuda_fp16.h>

// Problem constants (fixed by the dataset): B=16384, F=256, T=512, D=7, C=4
#define N_FEATS     256
#define N_TREES     512
#define DEPTH       7
#define TOTAL_NODES 130048      // T * (2^(D+1) - 2)
#define N_LEAVES    131072      // T * 2^(D+1)
#define MAX_B       16384

// Level offsets: off(l) = T*(2^l - 2). Levels 1..4 occupy [0, 15360).
#define SHALLOW_NODES 15360     // 512*(2+4+8+16)
#define DEEP_NODES    114688    // 512*(32+64+128)

#define TPB             512      // 16 warps: reg-limited 3 CTAs/SM -> 48 warps
#define WARPS_PER_CTA   16       //   with only 109KB smem -> ~119KB L1D
#define SAMPLES_PER_CTA 32
#define HALVES          2
#define TREES_PER_HALF  (N_TREES / HALVES)                 // 256
#define TREES_PER_WARP  (TREES_PER_HALF / WARPS_PER_CTA)   // 16
#define NT              8        // ILP sweet spot (16 spills — round 11)
#define PREP_TPB        256

// Levels 1-4: fused (feature, f32 bias) int2 — per-tree block <= 1 line.
__device__ int2 g_packed14[SHALLOW_NODES];
// Levels 5-7: feature ids as u8 — level-7 per-tree block = 128B = ONE line.
__device__ unsigned char g_feat_u8[DEEP_NODES];
// Leaf table as half4 (8B). Value-only compression, rel_err ~2e-4.
__device__ uint2 g_leaf_h[N_LEAVES];
// Per-half partial sums.
__device__ float4 g_part[HALVES * MAX_B];

// Prep (383 blocks — empirically fastest of 96/256/383 configs):
//  blk [0,15):    pack levels 1-4, 4 entries/thread   (15*256*4  = 15360)
//  blk [15,127):  u8 features l5-7, 4 entries/thread  (112*256*4 = 114688)
//  blk [127,383): leaf fp32->fp16, 2 leaves/thread    (256*256*2 = 131072)
__global__ __launch_bounds__(PREP_TPB) void prep_kernel(
    const int*    __restrict__ nodes,
    const float*  __restrict__ biases,
    const float4* __restrict__ leaf)
{
    const int blk = blockIdx.x;
    const int tid = threadIdx.x;
    if (blk < 15) {
        int i = (blk * PREP_TPB + tid) * 4;
        int4   n = __ldg((const int4*)(nodes + i));
        float4 b = __ldg((const float4*)(biases + i));
        int4 lo = make_int4(n.x, __float_as_int(b.x), n.y, __float_as_int(b.y));
        int4 hi = make_int4(n.z, __float_as_int(b.z), n.w, __float_as_int(b.w));
        int4* dst = (int4*)(g_packed14 + i);
        dst[0] = lo; dst[1] = hi;
    } else if (blk < 127) {
        int i = ((blk - 15) * PREP_TPB + tid) * 4;
        int4 n = __ldg((const int4*)(nodes + SHALLOW_NODES + i));
        unsigned v = (unsigned)(n.x & 255) | ((unsigned)(n.y & 255) << 8)
                   | ((unsigned)(n.z & 255) << 16) | ((unsigned)(n.w & 255) << 24);
        ((unsigned*)g_feat_u8)[i >> 2] = v;
    } else {
        int i = ((blk - 127) * PREP_TPB + tid) * 2;
        float4 v0 = __ldg(&leaf[i]);
        float4 v1 = __ldg(&leaf[i + 1]);
        __half2 h0 = __float22half2_rn(make_float2(v0.x, v0.y));
        __half2 h1 = __float22half2_rn(make_float2(v0.z, v0.w));
        __half2 h2 = __float22half2_rn(make_float2(v1.x, v1.y));
        __half2 h3 = __float22half2_rn(make_float2(v1.z, v1.w));
        uint4 o;
        o.x = *reinterpret_cast<unsigned*>(&h0);
        o.y = *reinterpret_cast<unsigned*>(&h1);
        o.z = *reinterpret_cast<unsigned*>(&h2);
        o.w = *reinterpret_cast<unsigned*>(&h3);
        ((uint4*)g_leaf_h)[i >> 1] = o;
    }
}

__global__ __launch_bounds__(TPB, 3) void tree_kernel(
    const float*  __restrict__ x,            // (B, 256) row-major
    const int*    __restrict__ root_nodes,   // (T,)
    const float*  __restrict__ root_biases,  // (T,)
    const int*    __restrict__ tree_indices, // (T,) = 2*t
    const float*  __restrict__ biases_flat,  // (TOTAL_NODES,) original
    int B)
{
    // Feature-major x tile: xs[f*32 + local_sample]; bank = local_sample ->
    // conflict-free LDS for arbitrary feature indices. Reused for reduction.
    __shared__ float xs[N_FEATS * SAMPLES_PER_CTA];   // 32 KB
    __shared__ float tmp[SAMPLES_PER_CTA][33];        // transpose tile

    const int tid  = threadIdx.x;
    const int lane = tid & 31;
    const int w    = tid >> 5;          // 0..15
    const int s0   = blockIdx.x * SAMPLES_PER_CTA;
    const int half = blockIdx.y;

    // In-CTA transpose staging: row-major gmem -> feature-major smem.
    // 16 warps: phase A covers 32 rows in 2 steps; phase B 32 cols in 2 steps.
    {
        const int cA = tid & 31;
        const int rA = tid >> 5;        // 0..15
        #pragma unroll
        for (int cf = 0; cf < N_FEATS; cf += 32) {
            #pragma unroll
            for (int k = 0; k < 2; k++) {
                int r = rA + k * 16;
                tmp[r][cA] = x[(s0 + r) * N_FEATS + cf + cA];
            }
            __syncthreads();
            #pragma unroll
            for (int k = 0; k < 2; k++) {
                int c = w + k * 16;
                xs[(cf + c) * 32 + lane] = tmp[lane][c];
            }
            __syncthreads();
        }
    }

    float a0 = 0.f, a1 = 0.f, a2 = 0.f, a3 = 0.f;
    const int tbase = half * TREES_PER_HALF + w * TREES_PER_WARP;

    // Per-warp root metadata: 16 trees in lanes 0..15, broadcast via shfl.
    int   rn_ti = 0;
    float rb_l  = 0.f;
    if (lane < TREES_PER_WARP) {
        rn_ti = __ldg(&root_nodes[tbase + lane])
              | (__ldg(&tree_indices[tbase + lane]) << 16);
        rb_l  = __ldg(&root_biases[tbase + lane]);
    }

    for (int tt = 0; tt < TREES_PER_WARP; tt += NT) {
        int idx[NT];

        #pragma unroll
        for (int j = 0; j < NT; j++) {
            int   m  = __shfl_sync(0xffffffffu, rn_ti, tt + j);
            float rb = __shfl_sync(0xffffffffu, rb_l,  tt + j);
            int   rf = m & 0xffff;
            int   ti = m >> 16;
            idx[j] = ti + (xs[rf * 32 + lane] < rb ? 1 : 0);
        }

        // Levels 1..7 (level-l block starts at T*(2^l - 2); idx is GLOBAL).
        // Branchless, independent gathers: MLP hides L1 latency.
        int off = 0;
        #pragma unroll
        for (int l = 1; l <= DEPTH; l++) {
            if (l <= 4) {
                #pragma unroll
                for (int j = 0; j < NT; j++) {
                    int2 e = __ldg(&g_packed14[off + idx[j]]);
                    float f = xs[e.x * 32 + lane];
                    idx[j] = 2 * idx[j] + (f < __int_as_float(e.y) ? 1 : 0);
                }
            } else {
                #pragma unroll
                for (int j = 0; j < NT; j++) {
                    int g = off + idx[j];
                    int fe = (int)__ldg(&g_feat_u8[g - SHALLOW_NODES]);
                    float b = __ldg(&biases_flat[g]);
                    float f = xs[fe * 32 + lane];
                    idx[j] = 2 * idx[j] + (f < b ? 1 : 0);
                }
            }
            off += N_TREES << l;
        }

        // Leaf accumulate: one LDG.64 (half4) per tree, fp32 accumulation.
        #pragma unroll
        for (int j = 0; j < NT; j++) {
            uint2 p = __ldg(&g_leaf_h[idx[j]]);
            float2 lo = __half22float2(*reinterpret_cast<__half2*>(&p.x));
            float2 hi = __half22float2(*reinterpret_cast<__half2*>(&p.y));
            a0 += lo.x; a1 += lo.y; a2 += hi.x; a3 += hi.y;
        }
    }

    // Deterministic cross-warp reduction (16 warps), reusing xs as scratch.
    __syncthreads();
    float* red = xs;
    red[(w * SAMPLES_PER_CTA + lane) * 4 + 0] = a0;
    red[(w * SAMPLES_PER_CTA + lane) * 4 + 1] = a1;
    red[(w * SAMPLES_PER_CTA + lane) * 4 + 2] = a2;
    red[(w * SAMPLES_PER_CTA + lane) * 4 + 3] = a3;
    __syncthreads();

    if (w == 0) {
        float4 r = make_float4(0.f, 0.f, 0.f, 0.f);
        #pragma unroll
        for (int ww = 0; ww < WARPS_PER_CTA; ww++) {
            const float* p = red + (ww * SAMPLES_PER_CTA + lane) * 4;
            r.x += p[0]; r.y += p[1]; r.z += p[2]; r.w += p[3];
        }
        g_part[half * B + s0 + lane] = r;
    }
}

__global__ void reduce_kernel(float4* __restrict__ out, int B) {
    int i = blockIdx.x * blockDim.x + threadIdx.x;
    if (i < B) {
        float4 a = g_part[i];
        float4 b = g_part[B + i];
        out[i] = make_float4(a.x + b.x, a.y + b.y, a.z + b.z, a.w + b.w);
    }
}

extern "C" void kernel_launch(void* const* d_in, const int* in_sizes, int n_in,
                              void* d_out, int out_size) {
    const float* x            = (const float*)d_in[0];
    const int*   root_nodes   = (const int*)  d_in[1];
    const float* root_biases  = (const float*)d_in[2];
    const int*   tree_indices = (const int*)  d_in[3];
    const int*   nodes_flat   = (const int*)  d_in[4];
    const float* biases_flat  = (const float*)d_in[5];
    const float4* leaf        = (const float4*)d_in[6];
    float4* out               = (float4*)d_out;

    const int B = in_sizes[0] / N_FEATS;   // 16384

    // 3 CTAs x 36.4KB = 109KB smem -> ~119KB L1D for the gather tables.
    // Carveout 50% (114KB window) admits the 3 reg-limited CTAs exactly.
    cudaFuncSetAttribute(tree_kernel,
                         cudaFuncAttributePreferredSharedMemoryCarveout, 50);

    prep_kernel<<<383, PREP_TPB>>>(nodes_flat, biases_flat, leaf);

    dim3 grid(B / SAMPLES_PER_CTA, HALVES);
    tree_kernel<<<grid, TPB>>>(x, root_nodes, root_biases, tree_indices,
                               biases_flat, B);

    reduce_kernel<<<(B + PREP_TPB - 1) / PREP_TPB, PREP_TPB>>>(out, B);
}